// round 5
// baseline (speedup 1.0000x reference)
#include <cuda_runtime.h>

#define NB   32    // batch
#define PM    4    // probe modes
#define NSL   8    // slices
#define NN  256    // ROI
#define LNS  16    // FFT lines per block (k_init/k_col/k_final: 256 thr)
#define LNSR  8    // FFT lines per block for k_row (128 thr)

// psi[b][pm][y][x]; state between kernels is Fr(psi) (row-FFT'd, natural order)
__device__ float2 g_psi[NB * PM * NN * NN];
// Ht[col][row] = (H[row][col]) / 256  (transposed for coalesced column access)
__device__ float2 g_Ht[NN * NN];

__device__ __forceinline__ float2 cmul(float2 a, float2 b) {
    return make_float2(fmaf(a.x, b.x, -a.y * b.y), fmaf(a.x, b.y, a.y * b.x));
}
// a * conj(b), same 4-FMA cost
__device__ __forceinline__ float2 cmulc(float2 a, float2 b) {
    return make_float2(fmaf(a.x, b.x, a.y * b.y), fmaf(a.y, b.x, -a.x * b.y));
}

// W16^m = exp(-2*pi*i*m/16), m = 0..9 (only k1*n2 in {0..9} used)
__constant__ float2 W16C[10] = {
    { 1.0f,          0.0f        },
    { 0.92387953f,  -0.38268343f },
    { 0.70710678f,  -0.70710678f },
    { 0.38268343f,  -0.92387953f },
    { 0.0f,         -1.0f        },
    {-0.38268343f,  -0.92387953f },
    {-0.70710678f,  -0.70710678f },
    {-0.92387953f,  -0.38268343f },
    {-1.0f,          0.0f        },
    {-0.92387953f,   0.38268343f },
};

template <bool INV>
__device__ __forceinline__ void bf4(float2& a, float2& b, float2& c, float2& d) {
    float2 t0 = make_float2(a.x + c.x, a.y + c.y);
    float2 t1 = make_float2(a.x - c.x, a.y - c.y);
    float2 t2 = make_float2(b.x + d.x, b.y + d.y);
    float2 t3 = make_float2(b.x - d.x, b.y - d.y);
    a = make_float2(t0.x + t2.x, t0.y + t2.y);
    c = make_float2(t0.x - t2.x, t0.y - t2.y);
    if (!INV) {
        b = make_float2(t1.x + t3.y, t1.y - t3.x);  // t1 - i*t3
        d = make_float2(t1.x - t3.y, t1.y + t3.x);  // t1 + i*t3
    } else {
        b = make_float2(t1.x - t3.y, t1.y + t3.x);
        d = make_float2(t1.x + t3.y, t1.y - t3.x);
    }
}

// 16-point DFT fully in registers. v is clobbered; out gets natural-order result.
template <bool INV>
__device__ __forceinline__ void fft16(float2* v, float2* out) {
#pragma unroll
    for (int n2 = 0; n2 < 4; n2++)
        bf4<INV>(v[n2], v[4 + n2], v[8 + n2], v[12 + n2]);
#pragma unroll
    for (int k1 = 1; k1 < 4; k1++)
#pragma unroll
        for (int n2 = 1; n2 < 4; n2++) {
            float2 w = W16C[k1 * n2];
            if (INV) w.y = -w.y;   // compile-time folded (INV is template const)
            v[4 * k1 + n2] = cmul(v[4 * k1 + n2], w);
        }
#pragma unroll
    for (int k1 = 0; k1 < 4; k1++)
        bf4<INV>(v[4 * k1 + 0], v[4 * k1 + 1], v[4 * k1 + 2], v[4 * k1 + 3]);
#pragma unroll
    for (int k1 = 0; k1 < 4; k1++)
#pragma unroll
        for (int k2 = 0; k2 < 4; k2++)
            out[k1 + 4 * k2] = v[4 * k1 + k2];
}

// Block-shared twiddle table: sTW[k1*16 + t] = W256^{k1*t} (forward sign).
__device__ __forceinline__ void init_tw256(float2* sTW, int flat, int nthr) {
    for (int i = flat; i < 256; i += nthr) {
        int k1 = i >> 4, t = i & 15;
        float s, c;
        sincospif(-(float)(k1 * t) * (1.0f / 128.0f), &s, &c);
        sTW[i] = make_float2(c, s);
    }
}

// 256-point FFT, 16 threads per line. reg[s] = element (16*s + t).
// tr: per-line 16x17 float2 transpose buffer — touched ONLY by this line's 16
// threads (within one warp) → __syncwarp suffices. Twiddles from shared table
// (no serial power chain); INV uses fused conjugate multiply.
template <bool INV>
__device__ __forceinline__ void fft256(float2 reg[16], int t, float2* tr,
                                       const float2* sTW) {
    float2 A[16];
    fft16<INV>(reg, A);
#pragma unroll
    for (int k1 = 1; k1 < 16; k1++) {
        float2 w = sTW[k1 * 16 + t];
        A[k1] = INV ? cmulc(A[k1], w) : cmul(A[k1], w);
    }
#pragma unroll
    for (int k1 = 0; k1 < 16; k1++) tr[k1 * 17 + t] = A[k1];
    __syncwarp();
    float2 B[16];
#pragma unroll
    for (int n2 = 0; n2 < 16; n2++) B[n2] = tr[t * 17 + n2];
    __syncwarp();
    fft16<INV>(B, reg);  // reg[k2] = X[16*k2 + t]
}

// ---------------------------------------------------------------------------
__global__ void k_prep(const float* __restrict__ Hr, const float* __restrict__ Hi) {
    int i = blockIdx.x * blockDim.x + threadIdx.x;
    int row = i >> 8, col = i & 255;
    g_Ht[(size_t)col * NN + row] =
        make_float2(Hr[i] * (1.0f / 256.0f), Hi[i] * (1.0f / 256.0f));
}

// ---------------------------------------------------------------------------
// k_init: psi = probe_translated * obj0, then forward row FFT.
// ---------------------------------------------------------------------------
__global__ __launch_bounds__(256, 2) void k_init(
    const float* __restrict__ obj, const float* __restrict__ probe,
    const float* __restrict__ shifts, const int* __restrict__ crop,
    const int* __restrict__ idxs) {
    __shared__ float2 buf[LNS * 272];
    __shared__ float2 sTW[256];
    int t = threadIdx.x, ly = threadIdx.y;
    init_tw256(sTW, ly * 16 + t, 256);
    int img = blockIdx.y;
    int b = img >> 2, pm = img & 3;
    int r = blockIdx.x * LNS + ly;

    int id = idxs[b];
    float tH = shifts[2 * id + 0];
    float tW = shifts[2 * id + 1];
    int p0 = crop[2 * id + 0];
    int p1 = crop[2 * id + 1];

    float ys = (float)r - tH;
    float y0f = floorf(ys);
    float wy = ys - y0f;
    int y0 = (int)y0f;

    float2 reg[16];
#pragma unroll
    for (int j = 0; j < 16; j++) {
        int c = 16 * j + t;
        float xs = (float)c - tW;
        float x0f = floorf(xs);
        float wx = xs - x0f;
        int x0 = (int)x0f;

        float amp = 0.f, ph = 0.f;
#pragma unroll
        for (int dy = 0; dy < 2; dy++) {
            int yy = y0 + dy;
            float wyt = dy ? wy : (1.f - wy);
            if (yy >= 0 && yy < NN) {
#pragma unroll
                for (int dx = 0; dx < 2; dx++) {
                    int xx = x0 + dx;
                    float w = wyt * (dx ? wx : (1.f - wx));
                    if (xx >= 0 && xx < NN) {
                        float2 v = *(const float2*)(probe +
                            ((size_t)(pm * NN + yy) * NN + xx) * 2);
                        amp = fmaf(w, v.x, amp);
                        ph  = fmaf(w, v.y, ph);
                    }
                }
            }
        }
        float sn, cs;
        __sincosf(ph, &sn, &cs);
        float2 pc = make_float2(amp * cs, amp * sn);

        float2 o = *(const float2*)(obj + (((size_t)(p0 + r)) * 1024 + (p1 + c)) * 2);
        float so, co;
        __sincosf(o.y, &so, &co);
        reg[j] = cmul(pc, make_float2(o.x * co, o.x * so));
    }
    __syncthreads();  // sTW visible

    fft256<false>(reg, t, buf + ly * 272, sTW);

    float2* dst = g_psi + ((size_t)img * NN + r) * NN;
#pragma unroll
    for (int k = 0; k < 16; k++) dst[16 * k + t] = reg[k];
}

// ---------------------------------------------------------------------------
// k_col: per column: Fc -> * (H/256) -> Fc^{-1}.
// ---------------------------------------------------------------------------
__global__ __launch_bounds__(256, 2) void k_col() {
    __shared__ float2 buf[LNS * 272];
    __shared__ float2 sTW[256];
    int t = threadIdx.x, ly = threadIdx.y;
    init_tw256(sTW, ly * 16 + t, 256);
    int img = blockIdx.y;
    int cb = blockIdx.x * LNS;
    float2* psi = g_psi + (size_t)img * NN * NN;

#pragma unroll
    for (int it = 0; it < 16; it++) {
        int row = it * 16 + ly;
        buf[row * 17 + t] = psi[row * NN + cb + t];
    }
    __syncthreads();
    float2 reg[16];
#pragma unroll
    for (int j = 0; j < 16; j++) reg[j] = buf[(16 * j + t) * 17 + ly];
    __syncthreads();

    fft256<false>(reg, t, buf + ly * 272, sTW);

    const float2* hcol = g_Ht + (size_t)(cb + ly) * NN;
#pragma unroll
    for (int k = 0; k < 16; k++) reg[k] = cmul(reg[k], hcol[16 * k + t]);

    fft256<true>(reg, t, buf + ly * 272, sTW);

    __syncthreads();  // fft done everywhere before reusing buf cross-line
#pragma unroll
    for (int k = 0; k < 16; k++) buf[(16 * k + t) * 17 + ly] = reg[k];
    __syncthreads();
#pragma unroll
    for (int it = 0; it < 16; it++) {
        int row = it * 16 + ly;
        psi[row * NN + cb + t] = buf[row * 17 + t];
    }
}

// ---------------------------------------------------------------------------
// k_row: per row: Fr^{-1}/256 -> * obj_z -> Fr. 8 lines / 128 threads.
// obj factor cached in line-local smem; FFTs warp-synchronous.
// ---------------------------------------------------------------------------
__global__ __launch_bounds__(128, 4) void k_row(
    const float* __restrict__ obj, const int* __restrict__ crop,
    const int* __restrict__ idxs, int z) {
    __shared__ float2 buf[LNSR * 272];
    __shared__ float2 sOC[LNSR * 256];
    __shared__ float2 sTW[256];
    int t = threadIdx.x, ly = threadIdx.y;
    init_tw256(sTW, ly * 16 + t, 128);
    int b = blockIdx.y;
    int r = blockIdx.x * LNSR + ly;

    int id = idxs[b];
    int p0 = crop[2 * id + 0];
    int p1 = crop[2 * id + 1];
    const float inv = 1.0f / 256.0f;

    float2* oc = sOC + ly * 256;
#pragma unroll
    for (int j = 0; j < 16; j++) {
        int c = 16 * j + t;
        float2 o = *(const float2*)(obj +
            (((size_t)z * 1024 + p0 + r) * 1024 + (p1 + c)) * 2);
        float so, co;
        __sincosf(o.y, &so, &co);
        oc[c] = make_float2(o.x * co * inv, o.x * so * inv);
    }
    __syncthreads();  // sTW + sOC visible

    for (int pm = 0; pm < PM; pm++) {
        float2* psi = g_psi + ((size_t)(b * PM + pm) * NN + r) * NN;
        float2 reg[16];
#pragma unroll
        for (int k = 0; k < 16; k++) reg[k] = psi[16 * k + t];

        fft256<true>(reg, t, buf + ly * 272, sTW);
#pragma unroll
        for (int j = 0; j < 16; j++) reg[j] = cmul(reg[j], oc[16 * j + t]);
        fft256<false>(reg, t, buf + ly * 272, sTW);

#pragma unroll
        for (int k = 0; k < 16; k++) psi[16 * k + t] = reg[k];
    }
}

// ---------------------------------------------------------------------------
// k_final: per column: Fc, accumulate |.|^2 over 4 probe modes, write dp.
// ---------------------------------------------------------------------------
__global__ __launch_bounds__(256, 2) void k_final(float* __restrict__ out) {
    __shared__ float2 buf[LNS * 272];
    __shared__ float2 sTW[256];
    int t = threadIdx.x, ly = threadIdx.y;
    init_tw256(sTW, ly * 16 + t, 256);
    int b = blockIdx.y;
    int cb = blockIdx.x * LNS;

    float acc[16];
#pragma unroll
    for (int k = 0; k < 16; k++) acc[k] = 0.f;

    for (int pm = 0; pm < PM; pm++) {
        float2* psi = g_psi + (size_t)(b * PM + pm) * NN * NN;
#pragma unroll
        for (int it = 0; it < 16; it++) {
            int row = it * 16 + ly;
            buf[row * 17 + t] = psi[row * NN + cb + t];
        }
        __syncthreads();
        float2 reg[16];
#pragma unroll
        for (int j = 0; j < 16; j++) reg[j] = buf[(16 * j + t) * 17 + ly];
        __syncthreads();

        fft256<false>(reg, t, buf + ly * 272, sTW);
#pragma unroll
        for (int k = 0; k < 16; k++)
            acc[k] = fmaf(reg[k].x, reg[k].x, fmaf(reg[k].y, reg[k].y, acc[k]));
        __syncthreads();  // buf reuse next pm (cross-line staging)
    }

    float* bf = (float*)buf;
#pragma unroll
    for (int k = 0; k < 16; k++) bf[(16 * k + t) * 17 + ly] = acc[k];
    __syncthreads();
#pragma unroll
    for (int it = 0; it < 16; it++) {
        int row = it * 16 + ly;
        out[(size_t)b * NN * NN + row * NN + cb + t] = bf[row * 17 + t];
    }
}

// ---------------------------------------------------------------------------
extern "C" void kernel_launch(void* const* d_in, const int* in_sizes, int n_in,
                              void* d_out, int out_size) {
    const float* obj    = (const float*)d_in[0];  // (1,8,1024,1024,2)
    const float* probe  = (const float*)d_in[1];  // (4,256,256,2)
    const float* shifts = (const float*)d_in[2];  // (1024,2)
    const int*   crop   = (const int*)d_in[3];    // (1024,2)
    const float* Hr     = (const float*)d_in[4];  // (256,256)
    const float* Hi     = (const float*)d_in[5];  // (256,256)
    const int*   idxs   = (const int*)d_in[6];    // (32,)
    float* out = (float*)d_out;                   // (32,256,256)

    k_prep<<<256, 256>>>(Hr, Hi);
    k_init<<<dim3(NN / LNS, NB * PM), dim3(16, LNS)>>>(obj, probe, shifts, crop, idxs);
    for (int z = 0; z < NSL - 1; z++) {
        k_col<<<dim3(NN / LNS, NB * PM), dim3(16, LNS)>>>();
        k_row<<<dim3(NN / LNSR, NB), dim3(16, LNSR)>>>(obj, crop, idxs, z + 1);
    }
    k_final<<<dim3(NN / LNS, NB), dim3(16, LNS)>>>(out);
}

// round 7
// speedup vs baseline: 1.0917x; 1.0917x over previous
#include <cuda_runtime.h>

#define NB   32    // batch
#define PM    4    // probe modes
#define NSL   8    // slices
#define NN  256    // ROI
#define LNS  16    // FFT lines per block (k_init/k_col/k_final: 256 thr)
#define LNSR  8    // FFT lines per block for k_row (128 thr)

// psi[b][pm][y][x]; state between kernels is Fr(psi) (row-FFT'd, natural order)
__device__ float2 g_psi[NB * PM * NN * NN];
// Ht[col][row] = (H[row][col]) / 256  (transposed for coalesced column access)
__device__ float2 g_Ht[NN * NN];

__device__ __forceinline__ float2 cmul(float2 a, float2 b) {
    return make_float2(fmaf(a.x, b.x, -a.y * b.y), fmaf(a.x, b.y, a.y * b.x));
}
// a * conj(b), same 4-FMA cost
__device__ __forceinline__ float2 cmulc(float2 a, float2 b) {
    return make_float2(fmaf(a.x, b.x, a.y * b.y), fmaf(a.y, b.x, -a.x * b.y));
}

// W16^m = exp(-2*pi*i*m/16), m = 0..9 (only k1*n2 in {0..9} used)
__constant__ float2 W16C[10] = {
    { 1.0f,          0.0f        },
    { 0.92387953f,  -0.38268343f },
    { 0.70710678f,  -0.70710678f },
    { 0.38268343f,  -0.92387953f },
    { 0.0f,         -1.0f        },
    {-0.38268343f,  -0.92387953f },
    {-0.70710678f,  -0.70710678f },
    {-0.92387953f,  -0.38268343f },
    {-1.0f,          0.0f        },
    {-0.92387953f,   0.38268343f },
};

template <bool INV>
__device__ __forceinline__ void bf4(float2& a, float2& b, float2& c, float2& d) {
    float2 t0 = make_float2(a.x + c.x, a.y + c.y);
    float2 t1 = make_float2(a.x - c.x, a.y - c.y);
    float2 t2 = make_float2(b.x + d.x, b.y + d.y);
    float2 t3 = make_float2(b.x - d.x, b.y - d.y);
    a = make_float2(t0.x + t2.x, t0.y + t2.y);
    c = make_float2(t0.x - t2.x, t0.y - t2.y);
    if (!INV) {
        b = make_float2(t1.x + t3.y, t1.y - t3.x);  // t1 - i*t3
        d = make_float2(t1.x - t3.y, t1.y + t3.x);  // t1 + i*t3
    } else {
        b = make_float2(t1.x - t3.y, t1.y + t3.x);
        d = make_float2(t1.x + t3.y, t1.y - t3.x);
    }
}

// 16-point DFT fully in registers. v is clobbered; out gets natural-order result.
template <bool INV>
__device__ __forceinline__ void fft16(float2* v, float2* out) {
#pragma unroll
    for (int n2 = 0; n2 < 4; n2++)
        bf4<INV>(v[n2], v[4 + n2], v[8 + n2], v[12 + n2]);
#pragma unroll
    for (int k1 = 1; k1 < 4; k1++)
#pragma unroll
        for (int n2 = 1; n2 < 4; n2++) {
            float2 w = W16C[k1 * n2];
            if (INV) w.y = -w.y;   // compile-time folded
            v[4 * k1 + n2] = cmul(v[4 * k1 + n2], w);
        }
#pragma unroll
    for (int k1 = 0; k1 < 4; k1++)
        bf4<INV>(v[4 * k1 + 0], v[4 * k1 + 1], v[4 * k1 + 2], v[4 * k1 + 3]);
#pragma unroll
    for (int k1 = 0; k1 < 4; k1++)
#pragma unroll
        for (int k2 = 0; k2 < 4; k2++)
            out[k1 + 4 * k2] = v[4 * k1 + k2];
}

// Per-thread twiddle powers tw[k-1] = W256^{t*k}, k=1..15 (forward sign).
// Log-depth product tree: 15 cmuls, dependency depth 4, all in registers.
__device__ __forceinline__ void make_tw256(float2* tw, int t) {
    float s, c;
    sincospif(-(float)t * (1.0f / 128.0f), &s, &c);
    float2 w1 = make_float2(c, s);
    float2 w2 = cmul(w1, w1);
    float2 w3 = cmul(w1, w2);
    float2 w4 = cmul(w2, w2);
    float2 w5 = cmul(w1, w4);
    float2 w6 = cmul(w2, w4);
    float2 w7 = cmul(w3, w4);
    float2 w8 = cmul(w4, w4);
    tw[0] = w1;  tw[1] = w2;  tw[2] = w3;  tw[3] = w4;
    tw[4] = w5;  tw[5] = w6;  tw[6] = w7;  tw[7] = w8;
    tw[8]  = cmul(w1, w8);
    tw[9]  = cmul(w2, w8);
    tw[10] = cmul(w3, w8);
    tw[11] = cmul(w4, w8);
    tw[12] = cmul(w5, w8);
    tw[13] = cmul(w6, w8);
    tw[14] = cmul(w7, w8);
}

// 256-point FFT, 16 threads per line. reg[s] = element (16*s + t).
// tr: per-line 16x17 float2 transpose buffer — touched ONLY by this line's 16
// threads (within one warp) → __syncwarp suffices. Twiddles from register
// array tw (hoisted by caller); INV conjugates at use (fused, free).
template <bool INV>
__device__ __forceinline__ void fft256(float2 reg[16], int t, float2* tr,
                                       const float2* tw) {
    float2 A[16];
    fft16<INV>(reg, A);
#pragma unroll
    for (int k1 = 1; k1 < 16; k1++)
        A[k1] = INV ? cmulc(A[k1], tw[k1 - 1]) : cmul(A[k1], tw[k1 - 1]);
#pragma unroll
    for (int k1 = 0; k1 < 16; k1++) tr[k1 * 17 + t] = A[k1];
    __syncwarp();
    float2 B[16];
#pragma unroll
    for (int n2 = 0; n2 < 16; n2++) B[n2] = tr[t * 17 + n2];
    __syncwarp();
    fft16<INV>(B, reg);  // reg[k2] = X[16*k2 + t]
}

// ---------------------------------------------------------------------------
__global__ void k_prep(const float* __restrict__ Hr, const float* __restrict__ Hi) {
    int i = blockIdx.x * blockDim.x + threadIdx.x;
    int row = i >> 8, col = i & 255;
    g_Ht[(size_t)col * NN + row] =
        make_float2(Hr[i] * (1.0f / 256.0f), Hi[i] * (1.0f / 256.0f));
}

// ---------------------------------------------------------------------------
// k_init: psi = probe_translated * obj0, then forward row FFT.
// Fully warp-synchronous (all smem is line-local).
// ---------------------------------------------------------------------------
__global__ __launch_bounds__(256, 2) void k_init(
    const float* __restrict__ obj, const float* __restrict__ probe,
    const float* __restrict__ shifts, const int* __restrict__ crop,
    const int* __restrict__ idxs) {
    __shared__ float2 buf[LNS * 272];
    int t = threadIdx.x, ly = threadIdx.y;
    int img = blockIdx.y;
    int b = img >> 2, pm = img & 3;
    int r = blockIdx.x * LNS + ly;

    int id = idxs[b];
    float tH = shifts[2 * id + 0];
    float tW = shifts[2 * id + 1];
    int p0 = crop[2 * id + 0];
    int p1 = crop[2 * id + 1];

    float ys = (float)r - tH;
    float y0f = floorf(ys);
    float wy = ys - y0f;
    int y0 = (int)y0f;

    float2 reg[16];
#pragma unroll
    for (int j = 0; j < 16; j++) {
        int c = 16 * j + t;
        float xs = (float)c - tW;
        float x0f = floorf(xs);
        float wx = xs - x0f;
        int x0 = (int)x0f;

        float amp = 0.f, ph = 0.f;
#pragma unroll
        for (int dy = 0; dy < 2; dy++) {
            int yy = y0 + dy;
            float wyt = dy ? wy : (1.f - wy);
            if (yy >= 0 && yy < NN) {
#pragma unroll
                for (int dx = 0; dx < 2; dx++) {
                    int xx = x0 + dx;
                    float w = wyt * (dx ? wx : (1.f - wx));
                    if (xx >= 0 && xx < NN) {
                        float2 v = *(const float2*)(probe +
                            ((size_t)(pm * NN + yy) * NN + xx) * 2);
                        amp = fmaf(w, v.x, amp);
                        ph  = fmaf(w, v.y, ph);
                    }
                }
            }
        }
        float sn, cs;
        __sincosf(ph, &sn, &cs);
        float2 pc = make_float2(amp * cs, amp * sn);

        float2 o = *(const float2*)(obj + (((size_t)(p0 + r)) * 1024 + (p1 + c)) * 2);
        float so, co;
        __sincosf(o.y, &so, &co);
        reg[j] = cmul(pc, make_float2(o.x * co, o.x * so));
    }

    float2 tw[15];
    make_tw256(tw, t);
    fft256<false>(reg, t, buf + ly * 272, tw);

    float2* dst = g_psi + ((size_t)img * NN + r) * NN;
#pragma unroll
    for (int k = 0; k < 16; k++) dst[16 * k + t] = reg[k];
}

// ---------------------------------------------------------------------------
// k_col: per column: Fc -> * (H/256) -> Fc^{-1}. Twiddle powers computed once
// and shared by both FFTs.
// ---------------------------------------------------------------------------
__global__ __launch_bounds__(256, 2) void k_col() {
    __shared__ float2 buf[LNS * 272];
    int t = threadIdx.x, ly = threadIdx.y;
    int img = blockIdx.y;
    int cb = blockIdx.x * LNS;
    float2* psi = g_psi + (size_t)img * NN * NN;

#pragma unroll
    for (int it = 0; it < 16; it++) {
        int row = it * 16 + ly;
        buf[row * 17 + t] = psi[row * NN + cb + t];
    }
    __syncthreads();
    float2 reg[16];
#pragma unroll
    for (int j = 0; j < 16; j++) reg[j] = buf[(16 * j + t) * 17 + ly];
    __syncthreads();

    float2 tw[15];
    make_tw256(tw, t);
    fft256<false>(reg, t, buf + ly * 272, tw);

    const float2* hcol = g_Ht + (size_t)(cb + ly) * NN;
#pragma unroll
    for (int k = 0; k < 16; k++) reg[k] = cmul(reg[k], hcol[16 * k + t]);

    fft256<true>(reg, t, buf + ly * 272, tw);

    __syncthreads();  // fft done everywhere before reusing buf cross-line
#pragma unroll
    for (int k = 0; k < 16; k++) buf[(16 * k + t) * 17 + ly] = reg[k];
    __syncthreads();
#pragma unroll
    for (int it = 0; it < 16; it++) {
        int row = it * 16 + ly;
        psi[row * NN + cb + t] = buf[row * 17 + t];
    }
}

// ---------------------------------------------------------------------------
// k_row: per row: Fr^{-1}/256 -> * obj_z -> Fr. 8 lines / 128 threads.
// obj factor in line-local smem; twiddles hoisted out of the pm loop.
// ---------------------------------------------------------------------------
__global__ __launch_bounds__(128, 4) void k_row(
    const float* __restrict__ obj, const int* __restrict__ crop,
    const int* __restrict__ idxs, int z) {
    __shared__ float2 buf[LNSR * 272];
    __shared__ float2 sOC[LNSR * 256];
    int t = threadIdx.x, ly = threadIdx.y;
    int b = blockIdx.y;
    int r = blockIdx.x * LNSR + ly;

    int id = idxs[b];
    int p0 = crop[2 * id + 0];
    int p1 = crop[2 * id + 1];
    const float inv = 1.0f / 256.0f;

    float2* oc = sOC + ly * 256;
#pragma unroll
    for (int j = 0; j < 16; j++) {
        int c = 16 * j + t;
        float2 o = *(const float2*)(obj +
            (((size_t)z * 1024 + p0 + r) * 1024 + (p1 + c)) * 2);
        float so, co;
        __sincosf(o.y, &so, &co);
        oc[c] = make_float2(o.x * co * inv, o.x * so * inv);
    }
    __syncwarp();

    float2 tw[15];
    make_tw256(tw, t);

    for (int pm = 0; pm < PM; pm++) {
        float2* psi = g_psi + ((size_t)(b * PM + pm) * NN + r) * NN;
        float2 reg[16];
#pragma unroll
        for (int k = 0; k < 16; k++) reg[k] = psi[16 * k + t];

        fft256<true>(reg, t, buf + ly * 272, tw);
#pragma unroll
        for (int j = 0; j < 16; j++) reg[j] = cmul(reg[j], oc[16 * j + t]);
        fft256<false>(reg, t, buf + ly * 272, tw);

#pragma unroll
        for (int k = 0; k < 16; k++) psi[16 * k + t] = reg[k];
    }
}

// ---------------------------------------------------------------------------
// k_final: per column: Fc, accumulate |.|^2 over 4 probe modes, write dp.
// ---------------------------------------------------------------------------
__global__ __launch_bounds__(256, 2) void k_final(float* __restrict__ out) {
    __shared__ float2 buf[LNS * 272];
    int t = threadIdx.x, ly = threadIdx.y;
    int b = blockIdx.y;
    int cb = blockIdx.x * LNS;

    float2 tw[15];
    make_tw256(tw, t);

    float acc[16];
#pragma unroll
    for (int k = 0; k < 16; k++) acc[k] = 0.f;

    for (int pm = 0; pm < PM; pm++) {
        float2* psi = g_psi + (size_t)(b * PM + pm) * NN * NN;
#pragma unroll
        for (int it = 0; it < 16; it++) {
            int row = it * 16 + ly;
            buf[row * 17 + t] = psi[row * NN + cb + t];
        }
        __syncthreads();
        float2 reg[16];
#pragma unroll
        for (int j = 0; j < 16; j++) reg[j] = buf[(16 * j + t) * 17 + ly];
        __syncthreads();

        fft256<false>(reg, t, buf + ly * 272, tw);
#pragma unroll
        for (int k = 0; k < 16; k++)
            acc[k] = fmaf(reg[k].x, reg[k].x, fmaf(reg[k].y, reg[k].y, acc[k]));
        __syncthreads();  // buf reuse next pm (cross-line staging)
    }

    float* bf = (float*)buf;
#pragma unroll
    for (int k = 0; k < 16; k++) bf[(16 * k + t) * 17 + ly] = acc[k];
    __syncthreads();
#pragma unroll
    for (int it = 0; it < 16; it++) {
        int row = it * 16 + ly;
        out[(size_t)b * NN * NN + row * NN + cb + t] = bf[row * 17 + t];
    }
}

// ---------------------------------------------------------------------------
extern "C" void kernel_launch(void* const* d_in, const int* in_sizes, int n_in,
                              void* d_out, int out_size) {
    const float* obj    = (const float*)d_in[0];  // (1,8,1024,1024,2)
    const float* probe  = (const float*)d_in[1];  // (4,256,256,2)
    const float* shifts = (const float*)d_in[2];  // (1024,2)
    const int*   crop   = (const int*)d_in[3];    // (1024,2)
    const float* Hr     = (const float*)d_in[4];  // (256,256)
    const float* Hi     = (const float*)d_in[5];  // (256,256)
    const int*   idxs   = (const int*)d_in[6];    // (32,)
    float* out = (float*)d_out;                   // (32,256,256)

    k_prep<<<256, 256>>>(Hr, Hi);
    k_init<<<dim3(NN / LNS, NB * PM), dim3(16, LNS)>>>(obj, probe, shifts, crop, idxs);
    for (int z = 0; z < NSL - 1; z++) {
        k_col<<<dim3(NN / LNS, NB * PM), dim3(16, LNS)>>>();
        k_row<<<dim3(NN / LNSR, NB), dim3(16, LNSR)>>>(obj, crop, idxs, z + 1);
    }
    k_final<<<dim3(NN / LNS, NB), dim3(16, LNS)>>>(out);
}

// round 8
// speedup vs baseline: 1.1044x; 1.0116x over previous
#include <cuda_runtime.h>

#define NB   32    // batch
#define PM    4    // probe modes
#define NSL   8    // slices
#define NN  256    // ROI
#define LNS  16    // FFT lines per block (k_init/k_col/k_final: 256 thr)
#define LNSR  8    // FFT lines per block for k_row (128 thr)

typedef unsigned long long u64;  // packed complex: lo=re, hi=im (f32x2)

// psi[b][pm][y][x]; state between kernels is Fr(psi) (row-FFT'd, natural order)
__device__ u64 g_psi[NB * PM * NN * NN];
// Ht[col][row] = (H[row][col]) / 256  (transposed for coalesced column access)
__device__ u64 g_Ht[NN * NN];

// ---- packed f32x2 complex primitives (sm_100a) ------------------------------
__device__ __forceinline__ u64 c_pack(float x, float y) {
    u64 r; asm("mov.b64 %0, {%1, %2};" : "=l"(r) : "f"(x), "f"(y)); return r;
}
__device__ __forceinline__ float2 c_unpack(u64 a) {
    float2 r; asm("mov.b64 {%0, %1}, %2;" : "=f"(r.x), "=f"(r.y) : "l"(a)); return r;
}
__device__ __forceinline__ u64 c_add(u64 a, u64 b) {
    u64 r; asm("add.rn.f32x2 %0, %1, %2;" : "=l"(r) : "l"(a), "l"(b)); return r;
}
__device__ __forceinline__ u64 c_sub(u64 a, u64 b) {
    u64 r; asm("sub.rn.f32x2 %0, %1, %2;" : "=l"(r) : "l"(a), "l"(b)); return r;
}
// multiply by -i: (x,y) -> (y,-x)
__device__ __forceinline__ u64 c_mi(u64 a) {
    float2 v = c_unpack(a);
    return c_pack(v.y, -v.x);
}
// general complex multiply (scalar lanes, 4 FFMA)
__device__ __forceinline__ u64 cmul_u(u64 a, u64 b) {
    float2 A = c_unpack(a), B = c_unpack(b);
    return c_pack(fmaf(A.x, B.x, -A.y * B.y), fmaf(A.x, B.y, A.y * B.x));
}
// a * w (float2 twiddle), conj(w) when INV
template <bool INV>
__device__ __forceinline__ u64 twmul(u64 a, float2 w) {
    float2 A = c_unpack(a);
    float wy = INV ? -w.y : w.y;
    return c_pack(fmaf(A.x, w.x, -A.y * wy), fmaf(A.x, wy, A.y * w.x));
}
// scalar complex mul (for twiddle-tree setup)
__device__ __forceinline__ float2 cmul(float2 a, float2 b) {
    return make_float2(fmaf(a.x, b.x, -a.y * b.y), fmaf(a.x, b.y, a.y * b.x));
}

// W16^m = exp(-2*pi*i*m/16), m = 0..9 (only k1*n2 in {0..9} used)
__constant__ float2 W16C[10] = {
    { 1.0f,          0.0f        },
    { 0.92387953f,  -0.38268343f },
    { 0.70710678f,  -0.70710678f },
    { 0.38268343f,  -0.92387953f },
    { 0.0f,         -1.0f        },
    {-0.38268343f,  -0.92387953f },
    {-0.70710678f,  -0.70710678f },
    {-0.92387953f,  -0.38268343f },
    {-1.0f,          0.0f        },
    {-0.92387953f,   0.38268343f },
};

// Radix-4 butterfly on packed complexes. Forward: b' = t1 - i*t3, d' = t1 + i*t3.
template <bool INV>
__device__ __forceinline__ void bf4p(u64& a, u64& b, u64& c, u64& d) {
    u64 t0 = c_add(a, c), t1 = c_sub(a, c);
    u64 t2 = c_add(b, d), t3 = c_sub(b, d);
    a = c_add(t0, t2);
    c = c_sub(t0, t2);
    u64 m = c_mi(t3);                      // (t3.y, -t3.x) = -i*t3
    if (!INV) { b = c_add(t1, m); d = c_sub(t1, m); }
    else      { b = c_sub(t1, m); d = c_add(t1, m); }
}

// 16-point DFT fully in registers (packed). v clobbered; out natural order.
template <bool INV>
__device__ __forceinline__ void fft16p(u64* v, u64* out) {
#pragma unroll
    for (int n2 = 0; n2 < 4; n2++)
        bf4p<INV>(v[n2], v[4 + n2], v[8 + n2], v[12 + n2]);
#pragma unroll
    for (int k1 = 1; k1 < 4; k1++)
#pragma unroll
        for (int n2 = 1; n2 < 4; n2++)
            v[4 * k1 + n2] = twmul<INV>(v[4 * k1 + n2], W16C[k1 * n2]);
#pragma unroll
    for (int k1 = 0; k1 < 4; k1++)
        bf4p<INV>(v[4 * k1 + 0], v[4 * k1 + 1], v[4 * k1 + 2], v[4 * k1 + 3]);
#pragma unroll
    for (int k1 = 0; k1 < 4; k1++)
#pragma unroll
        for (int k2 = 0; k2 < 4; k2++)
            out[k1 + 4 * k2] = v[4 * k1 + k2];
}

// Per-thread twiddle powers tw[k-1] = W256^{t*k}, k=1..15 (forward sign).
// Log-depth product tree: 15 cmuls, dependency depth 4, all in registers.
__device__ __forceinline__ void make_tw256(float2* tw, int t) {
    float s, c;
    sincospif(-(float)t * (1.0f / 128.0f), &s, &c);
    float2 w1 = make_float2(c, s);
    float2 w2 = cmul(w1, w1);
    float2 w3 = cmul(w1, w2);
    float2 w4 = cmul(w2, w2);
    float2 w5 = cmul(w1, w4);
    float2 w6 = cmul(w2, w4);
    float2 w7 = cmul(w3, w4);
    float2 w8 = cmul(w4, w4);
    tw[0] = w1;  tw[1] = w2;  tw[2] = w3;  tw[3] = w4;
    tw[4] = w5;  tw[5] = w6;  tw[6] = w7;  tw[7] = w8;
    tw[8]  = cmul(w1, w8);
    tw[9]  = cmul(w2, w8);
    tw[10] = cmul(w3, w8);
    tw[11] = cmul(w4, w8);
    tw[12] = cmul(w5, w8);
    tw[13] = cmul(w6, w8);
    tw[14] = cmul(w7, w8);
}

// 256-point FFT, 16 threads per line. reg[s] = element (16*s + t).
// tr: per-line 16x17 u64 transpose buffer — line-local within one warp.
template <bool INV>
__device__ __forceinline__ void fft256p(u64 reg[16], int t, u64* tr,
                                        const float2* tw) {
    u64 A[16];
    fft16p<INV>(reg, A);
#pragma unroll
    for (int k1 = 1; k1 < 16; k1++)
        A[k1] = twmul<INV>(A[k1], tw[k1 - 1]);
#pragma unroll
    for (int k1 = 0; k1 < 16; k1++) tr[k1 * 17 + t] = A[k1];
    __syncwarp();
    u64 B[16];
#pragma unroll
    for (int n2 = 0; n2 < 16; n2++) B[n2] = tr[t * 17 + n2];
    __syncwarp();
    fft16p<INV>(B, reg);  // reg[k2] = X[16*k2 + t]
}

// ---------------------------------------------------------------------------
__global__ void k_prep(const float* __restrict__ Hr, const float* __restrict__ Hi) {
    int i = blockIdx.x * blockDim.x + threadIdx.x;
    int row = i >> 8, col = i & 255;
    g_Ht[(size_t)col * NN + row] =
        c_pack(Hr[i] * (1.0f / 256.0f), Hi[i] * (1.0f / 256.0f));
}

// ---------------------------------------------------------------------------
// k_init: psi = probe_translated * obj0, then forward row FFT.
// ---------------------------------------------------------------------------
__global__ __launch_bounds__(256, 2) void k_init(
    const float* __restrict__ obj, const float* __restrict__ probe,
    const float* __restrict__ shifts, const int* __restrict__ crop,
    const int* __restrict__ idxs) {
    __shared__ u64 buf[LNS * 272];
    int t = threadIdx.x, ly = threadIdx.y;
    int img = blockIdx.y;
    int b = img >> 2, pm = img & 3;
    int r = blockIdx.x * LNS + ly;

    int id = idxs[b];
    float tH = shifts[2 * id + 0];
    float tW = shifts[2 * id + 1];
    int p0 = crop[2 * id + 0];
    int p1 = crop[2 * id + 1];

    float ys = (float)r - tH;
    float y0f = floorf(ys);
    float wy = ys - y0f;
    int y0 = (int)y0f;

    u64 reg[16];
#pragma unroll
    for (int j = 0; j < 16; j++) {
        int c = 16 * j + t;
        float xs = (float)c - tW;
        float x0f = floorf(xs);
        float wx = xs - x0f;
        int x0 = (int)x0f;

        float amp = 0.f, ph = 0.f;
#pragma unroll
        for (int dy = 0; dy < 2; dy++) {
            int yy = y0 + dy;
            float wyt = dy ? wy : (1.f - wy);
            if (yy >= 0 && yy < NN) {
#pragma unroll
                for (int dx = 0; dx < 2; dx++) {
                    int xx = x0 + dx;
                    float w = wyt * (dx ? wx : (1.f - wx));
                    if (xx >= 0 && xx < NN) {
                        float2 v = *(const float2*)(probe +
                            ((size_t)(pm * NN + yy) * NN + xx) * 2);
                        amp = fmaf(w, v.x, amp);
                        ph  = fmaf(w, v.y, ph);
                    }
                }
            }
        }
        float sn, cs;
        __sincosf(ph, &sn, &cs);
        float2 pc = make_float2(amp * cs, amp * sn);

        float2 o = *(const float2*)(obj + (((size_t)(p0 + r)) * 1024 + (p1 + c)) * 2);
        float so, co;
        __sincosf(o.y, &so, &co);
        float2 oc = make_float2(o.x * co, o.x * so);
        reg[j] = c_pack(fmaf(pc.x, oc.x, -pc.y * oc.y),
                        fmaf(pc.x, oc.y,  pc.y * oc.x));
    }

    float2 tw[15];
    make_tw256(tw, t);
    fft256p<false>(reg, t, buf + ly * 272, tw);

    u64* dst = g_psi + ((size_t)img * NN + r) * NN;
#pragma unroll
    for (int k = 0; k < 16; k++) dst[16 * k + t] = reg[k];
}

// ---------------------------------------------------------------------------
// k_col: per column: Fc -> * (H/256) -> Fc^{-1}.
// ---------------------------------------------------------------------------
__global__ __launch_bounds__(256, 2) void k_col() {
    __shared__ u64 buf[LNS * 272];
    int t = threadIdx.x, ly = threadIdx.y;
    int img = blockIdx.y;
    int cb = blockIdx.x * LNS;
    u64* psi = g_psi + (size_t)img * NN * NN;

#pragma unroll
    for (int it = 0; it < 16; it++) {
        int row = it * 16 + ly;
        buf[row * 17 + t] = psi[row * NN + cb + t];
    }
    __syncthreads();
    u64 reg[16];
#pragma unroll
    for (int j = 0; j < 16; j++) reg[j] = buf[(16 * j + t) * 17 + ly];
    __syncthreads();

    float2 tw[15];
    make_tw256(tw, t);
    fft256p<false>(reg, t, buf + ly * 272, tw);

    const u64* hcol = g_Ht + (size_t)(cb + ly) * NN;
#pragma unroll
    for (int k = 0; k < 16; k++) reg[k] = cmul_u(reg[k], hcol[16 * k + t]);

    fft256p<true>(reg, t, buf + ly * 272, tw);

    __syncthreads();  // fft done everywhere before reusing buf cross-line
#pragma unroll
    for (int k = 0; k < 16; k++) buf[(16 * k + t) * 17 + ly] = reg[k];
    __syncthreads();
#pragma unroll
    for (int it = 0; it < 16; it++) {
        int row = it * 16 + ly;
        psi[row * NN + cb + t] = buf[row * 17 + t];
    }
}

// ---------------------------------------------------------------------------
// k_row: per row: Fr^{-1}/256 -> * obj_z -> Fr. 8 lines / 128 threads.
// obj factor in line-local smem; twiddles hoisted out of the pm loop.
// ---------------------------------------------------------------------------
__global__ __launch_bounds__(128, 4) void k_row(
    const float* __restrict__ obj, const int* __restrict__ crop,
    const int* __restrict__ idxs, int z) {
    __shared__ u64 buf[LNSR * 272];
    __shared__ u64 sOC[LNSR * 256];
    int t = threadIdx.x, ly = threadIdx.y;
    int b = blockIdx.y;
    int r = blockIdx.x * LNSR + ly;

    int id = idxs[b];
    int p0 = crop[2 * id + 0];
    int p1 = crop[2 * id + 1];
    const float inv = 1.0f / 256.0f;

    u64* oc = sOC + ly * 256;
#pragma unroll
    for (int j = 0; j < 16; j++) {
        int c = 16 * j + t;
        float2 o = *(const float2*)(obj +
            (((size_t)z * 1024 + p0 + r) * 1024 + (p1 + c)) * 2);
        float so, co;
        __sincosf(o.y, &so, &co);
        oc[c] = c_pack(o.x * co * inv, o.x * so * inv);
    }
    __syncwarp();

    float2 tw[15];
    make_tw256(tw, t);

    for (int pm = 0; pm < PM; pm++) {
        u64* psi = g_psi + ((size_t)(b * PM + pm) * NN + r) * NN;
        u64 reg[16];
#pragma unroll
        for (int k = 0; k < 16; k++) reg[k] = psi[16 * k + t];

        fft256p<true>(reg, t, buf + ly * 272, tw);
#pragma unroll
        for (int j = 0; j < 16; j++) reg[j] = cmul_u(reg[j], oc[16 * j + t]);
        fft256p<false>(reg, t, buf + ly * 272, tw);

#pragma unroll
        for (int k = 0; k < 16; k++) psi[16 * k + t] = reg[k];
    }
}

// ---------------------------------------------------------------------------
// k_final: per column: Fc, accumulate |.|^2 over 4 probe modes, write dp.
// ---------------------------------------------------------------------------
__global__ __launch_bounds__(256, 2) void k_final(float* __restrict__ out) {
    __shared__ u64 buf[LNS * 272];
    int t = threadIdx.x, ly = threadIdx.y;
    int b = blockIdx.y;
    int cb = blockIdx.x * LNS;

    float2 tw[15];
    make_tw256(tw, t);

    float acc[16];
#pragma unroll
    for (int k = 0; k < 16; k++) acc[k] = 0.f;

    for (int pm = 0; pm < PM; pm++) {
        u64* psi = g_psi + (size_t)(b * PM + pm) * NN * NN;
#pragma unroll
        for (int it = 0; it < 16; it++) {
            int row = it * 16 + ly;
            buf[row * 17 + t] = psi[row * NN + cb + t];
        }
        __syncthreads();
        u64 reg[16];
#pragma unroll
        for (int j = 0; j < 16; j++) reg[j] = buf[(16 * j + t) * 17 + ly];
        __syncthreads();

        fft256p<false>(reg, t, buf + ly * 272, tw);
#pragma unroll
        for (int k = 0; k < 16; k++) {
            float2 v = c_unpack(reg[k]);
            acc[k] = fmaf(v.x, v.x, fmaf(v.y, v.y, acc[k]));
        }
        __syncthreads();  // buf reuse next pm (cross-line staging)
    }

    float* bf = (float*)buf;
#pragma unroll
    for (int k = 0; k < 16; k++) bf[(16 * k + t) * 17 + ly] = acc[k];
    __syncthreads();
#pragma unroll
    for (int it = 0; it < 16; it++) {
        int row = it * 16 + ly;
        out[(size_t)b * NN * NN + row * NN + cb + t] = bf[row * 17 + t];
    }
}

// ---------------------------------------------------------------------------
extern "C" void kernel_launch(void* const* d_in, const int* in_sizes, int n_in,
                              void* d_out, int out_size) {
    const float* obj    = (const float*)d_in[0];  // (1,8,1024,1024,2)
    const float* probe  = (const float*)d_in[1];  // (4,256,256,2)
    const float* shifts = (const float*)d_in[2];  // (1024,2)
    const int*   crop   = (const int*)d_in[3];    // (1024,2)
    const float* Hr     = (const float*)d_in[4];  // (256,256)
    const float* Hi     = (const float*)d_in[5];  // (256,256)
    const int*   idxs   = (const int*)d_in[6];    // (32,)
    float* out = (float*)d_out;                   // (32,256,256)

    k_prep<<<256, 256>>>(Hr, Hi);
    k_init<<<dim3(NN / LNS, NB * PM), dim3(16, LNS)>>>(obj, probe, shifts, crop, idxs);
    for (int z = 0; z < NSL - 1; z++) {
        k_col<<<dim3(NN / LNS, NB * PM), dim3(16, LNS)>>>();
        k_row<<<dim3(NN / LNSR, NB), dim3(16, LNSR)>>>(obj, crop, idxs, z + 1);
    }
    k_final<<<dim3(NN / LNS, NB), dim3(16, LNS)>>>(out);
}

// round 11
// speedup vs baseline: 1.2852x; 1.1636x over previous
#include <cuda_runtime.h>

#define NB   32    // batch
#define PM    4    // probe modes
#define NSL   8    // slices
#define NN  256    // ROI
#define LNS  16    // lines per block
#define LNSR  8    // lines per block for k_row (128 thr)

typedef unsigned long long u64;  // packed complex: lo=re, hi=im (f32x2)

// psi[b][pm][y][x]; state between kernels is Fr(psi) (row-FFT'd, natural order)
__device__ u64 g_psi[NB * PM * NN * NN];
// Hs[row][col] = H[row][col] / 256 (row-major, packed)
__device__ u64 g_Hs[NN * NN];

// ---- packed f32x2 complex primitives (sm_100a) ------------------------------
__device__ __forceinline__ u64 c_pack(float x, float y) {
    u64 r; asm("mov.b64 %0, {%1, %2};" : "=l"(r) : "f"(x), "f"(y)); return r;
}
__device__ __forceinline__ float2 c_unpack(u64 a) {
    float2 r; asm("mov.b64 {%0, %1}, %2;" : "=f"(r.x), "=f"(r.y) : "l"(a)); return r;
}
__device__ __forceinline__ u64 c_add(u64 a, u64 b) {
    u64 r; asm("add.rn.f32x2 %0, %1, %2;" : "=l"(r) : "l"(a), "l"(b)); return r;
}
__device__ __forceinline__ u64 c_sub(u64 a, u64 b) {
    u64 r; asm("sub.rn.f32x2 %0, %1, %2;" : "=l"(r) : "l"(a), "l"(b)); return r;
}
// multiply by -i: (x,y) -> (y,-x)
__device__ __forceinline__ u64 c_mi(u64 a) {
    float2 v = c_unpack(a);
    return c_pack(v.y, -v.x);
}
// general complex multiply (scalar lanes, 4 FFMA)
__device__ __forceinline__ u64 cmul_u(u64 a, u64 b) {
    float2 A = c_unpack(a), B = c_unpack(b);
    return c_pack(fmaf(A.x, B.x, -A.y * B.y), fmaf(A.x, B.y, A.y * B.x));
}
// a * w (float2 twiddle), conj(w) when INV
template <bool INV>
__device__ __forceinline__ u64 twmul(u64 a, float2 w) {
    float2 A = c_unpack(a);
    float wy = INV ? -w.y : w.y;
    return c_pack(fmaf(A.x, w.x, -A.y * wy), fmaf(A.x, wy, A.y * w.x));
}
// scalar complex mul (for twiddle-tree setup)
__device__ __forceinline__ float2 cmul(float2 a, float2 b) {
    return make_float2(fmaf(a.x, b.x, -a.y * b.y), fmaf(a.x, b.y, a.y * b.x));
}

// W16^m = exp(-2*pi*i*m/16), m = 0..9 (only k1*n2 in {0..9} used)
__constant__ float2 W16C[10] = {
    { 1.0f,          0.0f        },
    { 0.92387953f,  -0.38268343f },
    { 0.70710678f,  -0.70710678f },
    { 0.38268343f,  -0.92387953f },
    { 0.0f,         -1.0f        },
    {-0.38268343f,  -0.92387953f },
    {-0.70710678f,  -0.70710678f },
    {-0.92387953f,  -0.38268343f },
    {-1.0f,          0.0f        },
    {-0.92387953f,   0.38268343f },
};

// Radix-4 butterfly on packed complexes.
template <bool INV>
__device__ __forceinline__ void bf4p(u64& a, u64& b, u64& c, u64& d) {
    u64 t0 = c_add(a, c), t1 = c_sub(a, c);
    u64 t2 = c_add(b, d), t3 = c_sub(b, d);
    a = c_add(t0, t2);
    c = c_sub(t0, t2);
    u64 m = c_mi(t3);                      // -i*t3
    if (!INV) { b = c_add(t1, m); d = c_sub(t1, m); }
    else      { b = c_sub(t1, m); d = c_add(t1, m); }
}

// 16-point DFT fully in registers (packed). v clobbered; out natural order.
template <bool INV>
__device__ __forceinline__ void fft16p(u64* v, u64* out) {
#pragma unroll
    for (int n2 = 0; n2 < 4; n2++)
        bf4p<INV>(v[n2], v[4 + n2], v[8 + n2], v[12 + n2]);
#pragma unroll
    for (int k1 = 1; k1 < 4; k1++)
#pragma unroll
        for (int n2 = 1; n2 < 4; n2++)
            v[4 * k1 + n2] = twmul<INV>(v[4 * k1 + n2], W16C[k1 * n2]);
#pragma unroll
    for (int k1 = 0; k1 < 4; k1++)
        bf4p<INV>(v[4 * k1 + 0], v[4 * k1 + 1], v[4 * k1 + 2], v[4 * k1 + 3]);
#pragma unroll
    for (int k1 = 0; k1 < 4; k1++)
#pragma unroll
        for (int k2 = 0; k2 < 4; k2++)
            out[k1 + 4 * k2] = v[4 * k1 + k2];
}

// Per-thread twiddle powers tw[k-1] = W256^{j*k}, k=1..15 (forward sign).
__device__ __forceinline__ void make_tw256(float2* tw, int j) {
    float s, c;
    sincospif(-(float)j * (1.0f / 128.0f), &s, &c);
    float2 w1 = make_float2(c, s);
    float2 w2 = cmul(w1, w1);
    float2 w3 = cmul(w1, w2);
    float2 w4 = cmul(w2, w2);
    float2 w5 = cmul(w1, w4);
    float2 w6 = cmul(w2, w4);
    float2 w7 = cmul(w3, w4);
    float2 w8 = cmul(w4, w4);
    tw[0] = w1;  tw[1] = w2;  tw[2] = w3;  tw[3] = w4;
    tw[4] = w5;  tw[5] = w6;  tw[6] = w7;  tw[7] = w8;
    tw[8]  = cmul(w1, w8);
    tw[9]  = cmul(w2, w8);
    tw[10] = cmul(w3, w8);
    tw[11] = cmul(w4, w8);
    tw[12] = cmul(w5, w8);
    tw[13] = cmul(w6, w8);
    tw[14] = cmul(w7, w8);
}

// Warp-local 256-pt FFT: 16 threads per line all inside one warp (k_init/k_row).
// reg[s] = element (16*s + t); tr = per-line 16x17 buffer.
template <bool INV>
__device__ __forceinline__ void fft256p(u64 reg[16], int t, u64* tr,
                                        const float2* tw) {
    u64 A[16];
    fft16p<INV>(reg, A);
#pragma unroll
    for (int k1 = 1; k1 < 16; k1++)
        A[k1] = twmul<INV>(A[k1], tw[k1 - 1]);
#pragma unroll
    for (int k1 = 0; k1 < 16; k1++) tr[k1 * 17 + t] = A[k1];
    __syncwarp();
    u64 B[16];
#pragma unroll
    for (int n2 = 0; n2 < 16; n2++) B[n2] = tr[t * 17 + n2];
    __syncwarp();
    fft16p<INV>(B, reg);  // reg[k2] = X[16*k2 + t]
}

// Cross-warp 256-pt FFT for column kernels: line = threadIdx.x (ln), intra-line
// index j = threadIdx.y. reg[s] = element (16*s + j) of line ln.
// W layout: [(a*17 + b)*16 + ln] — conflict-free & coalesced both directions.
template <bool INV>
__device__ __forceinline__ void fft256blk(u64 reg[16], int j, int ln, u64* W,
                                          const float2* tw) {
    u64 A[16];
    fft16p<INV>(reg, A);
#pragma unroll
    for (int k1 = 1; k1 < 16; k1++)
        A[k1] = twmul<INV>(A[k1], tw[k1 - 1]);
#pragma unroll
    for (int k1 = 0; k1 < 16; k1++) W[(k1 * 17 + j) * 16 + ln] = A[k1];
    __syncthreads();
    u64 B[16];
#pragma unroll
    for (int n2 = 0; n2 < 16; n2++) B[n2] = W[(j * 17 + n2) * 16 + ln];
    __syncthreads();   // protects W for the next call
    fft16p<INV>(B, reg);  // reg[k2] = X[16*k2 + j]
}

// ---------------------------------------------------------------------------
__global__ void k_prep(const float* __restrict__ Hr, const float* __restrict__ Hi) {
    int i = blockIdx.x * blockDim.x + threadIdx.x;
    g_Hs[i] = c_pack(Hr[i] * (1.0f / 256.0f), Hi[i] * (1.0f / 256.0f));
}

// ---------------------------------------------------------------------------
// k_init: psi = probe_translated * obj0, then forward row FFT. Warp-sync.
// ---------------------------------------------------------------------------
__global__ __launch_bounds__(256, 2) void k_init(
    const float* __restrict__ obj, const float* __restrict__ probe,
    const float* __restrict__ shifts, const int* __restrict__ crop,
    const int* __restrict__ idxs) {
    __shared__ u64 buf[LNS * 272];
    int t = threadIdx.x, ly = threadIdx.y;
    int img = blockIdx.y;
    int b = img >> 2, pm = img & 3;
    int r = blockIdx.x * LNS + ly;

    int id = idxs[b];
    float tH = shifts[2 * id + 0];
    float tW = shifts[2 * id + 1];
    int p0 = crop[2 * id + 0];
    int p1 = crop[2 * id + 1];

    float ys = (float)r - tH;
    float y0f = floorf(ys);
    float wy = ys - y0f;
    int y0 = (int)y0f;

    u64 reg[16];
#pragma unroll
    for (int jj = 0; jj < 16; jj++) {
        int c = 16 * jj + t;
        float xs = (float)c - tW;
        float x0f = floorf(xs);
        float wx = xs - x0f;
        int x0 = (int)x0f;

        float amp = 0.f, ph = 0.f;
#pragma unroll
        for (int dy = 0; dy < 2; dy++) {
            int yy = y0 + dy;
            float wyt = dy ? wy : (1.f - wy);
            if (yy >= 0 && yy < NN) {
#pragma unroll
                for (int dx = 0; dx < 2; dx++) {
                    int xx = x0 + dx;
                    float w = wyt * (dx ? wx : (1.f - wx));
                    if (xx >= 0 && xx < NN) {
                        float2 v = *(const float2*)(probe +
                            ((size_t)(pm * NN + yy) * NN + xx) * 2);
                        amp = fmaf(w, v.x, amp);
                        ph  = fmaf(w, v.y, ph);
                    }
                }
            }
        }
        float sn, cs;
        __sincosf(ph, &sn, &cs);
        float2 pc = make_float2(amp * cs, amp * sn);

        float2 o = *(const float2*)(obj + (((size_t)(p0 + r)) * 1024 + (p1 + c)) * 2);
        float so, co;
        __sincosf(o.y, &so, &co);
        float2 oc = make_float2(o.x * co, o.x * so);
        reg[jj] = c_pack(fmaf(pc.x, oc.x, -pc.y * oc.y),
                         fmaf(pc.x, oc.y,  pc.y * oc.x));
    }

    float2 tw[15];
    make_tw256(tw, t);
    fft256p<false>(reg, t, buf + ly * 272, tw);

    u64* dst = g_psi + ((size_t)img * NN + r) * NN;
#pragma unroll
    for (int k = 0; k < 16; k++) dst[16 * k + t] = reg[k];
}

// ---------------------------------------------------------------------------
// k_col: per column: Fc -> * (H/256) -> Fc^{-1}. NO staging — thread t owns
// column cb+t; intra-FFT index j spans warps (block syncs inside fft256blk).
// All global accesses directly coalesced.
// ---------------------------------------------------------------------------
__global__ __launch_bounds__(256, 2) void k_col() {
    __shared__ u64 W[16 * 17 * 16];
    int t = threadIdx.x;   // column within tile (line)
    int j = threadIdx.y;   // intra-line FFT index
    int img = blockIdx.y;
    int cb = blockIdx.x * 16;
    u64* psi = g_psi + (size_t)img * NN * NN;

    u64 reg[16];
#pragma unroll
    for (int it = 0; it < 16; it++)
        reg[it] = psi[(size_t)(16 * it + j) * NN + cb + t];

    float2 tw[15];
    make_tw256(tw, j);
    fft256blk<false>(reg, j, t, W, tw);

#pragma unroll
    for (int k = 0; k < 16; k++)
        reg[k] = cmul_u(reg[k], g_Hs[(size_t)(16 * k + j) * NN + cb + t]);

    fft256blk<true>(reg, j, t, W, tw);

#pragma unroll
    for (int k = 0; k < 16; k++)
        psi[(size_t)(16 * k + j) * NN + cb + t] = reg[k];
}

// ---------------------------------------------------------------------------
// k_row: per row: Fr^{-1}/256 -> * obj_z -> Fr. 8 lines / 128 threads.
// obj factor in line-local smem; twiddles hoisted out of the pm loop.
// ---------------------------------------------------------------------------
__global__ __launch_bounds__(128, 4) void k_row(
    const float* __restrict__ obj, const int* __restrict__ crop,
    const int* __restrict__ idxs, int z) {
    __shared__ u64 buf[LNSR * 272];
    __shared__ u64 sOC[LNSR * 256];
    int t = threadIdx.x, ly = threadIdx.y;
    int b = blockIdx.y;
    int r = blockIdx.x * LNSR + ly;

    int id = idxs[b];
    int p0 = crop[2 * id + 0];
    int p1 = crop[2 * id + 1];
    const float inv = 1.0f / 256.0f;

    u64* oc = sOC + ly * 256;
#pragma unroll
    for (int jj = 0; jj < 16; jj++) {
        int c = 16 * jj + t;
        float2 o = *(const float2*)(obj +
            (((size_t)z * 1024 + p0 + r) * 1024 + (p1 + c)) * 2);
        float so, co;
        __sincosf(o.y, &so, &co);
        oc[c] = c_pack(o.x * co * inv, o.x * so * inv);
    }
    __syncwarp();

    float2 tw[15];
    make_tw256(tw, t);

    for (int pm = 0; pm < PM; pm++) {
        u64* psi = g_psi + ((size_t)(b * PM + pm) * NN + r) * NN;
        u64 reg[16];
#pragma unroll
        for (int k = 0; k < 16; k++) reg[k] = psi[16 * k + t];

        fft256p<true>(reg, t, buf + ly * 272, tw);
#pragma unroll
        for (int jj = 0; jj < 16; jj++) reg[jj] = cmul_u(reg[jj], oc[16 * jj + t]);
        fft256p<false>(reg, t, buf + ly * 272, tw);

#pragma unroll
        for (int k = 0; k < 16; k++) psi[16 * k + t] = reg[k];
    }
}

// ---------------------------------------------------------------------------
// k_final: per column: Fc, accumulate |.|^2 over 4 probe modes. NO staging —
// same column-owning layout as k_col; dp written directly coalesced.
// ---------------------------------------------------------------------------
__global__ __launch_bounds__(256, 2) void k_final(float* __restrict__ out) {
    __shared__ u64 W[16 * 17 * 16];
    int t = threadIdx.x;   // column within tile
    int j = threadIdx.y;   // intra-line FFT index
    int b = blockIdx.y;
    int cb = blockIdx.x * 16;

    float2 tw[15];
    make_tw256(tw, j);

    float acc[16];
#pragma unroll
    for (int k = 0; k < 16; k++) acc[k] = 0.f;

    for (int pm = 0; pm < PM; pm++) {
        u64* psi = g_psi + (size_t)(b * PM + pm) * NN * NN;
        u64 reg[16];
#pragma unroll
        for (int it = 0; it < 16; it++)
            reg[it] = psi[(size_t)(16 * it + j) * NN + cb + t];

        fft256blk<false>(reg, j, t, W, tw);

#pragma unroll
        for (int k = 0; k < 16; k++) {
            float2 v = c_unpack(reg[k]);
            acc[k] = fmaf(v.x, v.x, fmaf(v.y, v.y, acc[k]));
        }
    }

#pragma unroll
    for (int k = 0; k < 16; k++)
        out[(size_t)b * NN * NN + (size_t)(16 * k + j) * NN + cb + t] = acc[k];
}

// ---------------------------------------------------------------------------
extern "C" void kernel_launch(void* const* d_in, const int* in_sizes, int n_in,
                              void* d_out, int out_size) {
    const float* obj    = (const float*)d_in[0];  // (1,8,1024,1024,2)
    const float* probe  = (const float*)d_in[1];  // (4,256,256,2)
    const float* shifts = (const float*)d_in[2];  // (1024,2)
    const int*   crop   = (const int*)d_in[3];    // (1024,2)
    const float* Hr     = (const float*)d_in[4];  // (256,256)
    const float* Hi     = (const float*)d_in[5];  // (256,256)
    const int*   idxs   = (const int*)d_in[6];    // (32,)
    float* out = (float*)d_out;                   // (32,256,256)

    k_prep<<<256, 256>>>(Hr, Hi);
    k_init<<<dim3(NN / LNS, NB * PM), dim3(16, LNS)>>>(obj, probe, shifts, crop, idxs);
    for (int z = 0; z < NSL - 1; z++) {
        k_col<<<dim3(NN / 16, NB * PM), dim3(16, 16)>>>();
        k_row<<<dim3(NN / LNSR, NB), dim3(16, LNSR)>>>(obj, crop, idxs, z + 1);
    }
    k_final<<<dim3(NN / 16, NB), dim3(16, 16)>>>(out);
}